// round 1
// baseline (speedup 1.0000x reference)
#include <cuda_runtime.h>
#include <math.h>

#define D_MODEL 1024
#define B_SZ 8
#define S_LEN 1024
#define N_HEADS 16
#define D_HEAD 64
#define RANK 128
#define N_COMPRESS 64
#define N_QK 32
#define N_V 32
#define TOPK_C 8
#define TOPK_QK 4
#define TOPK_V 6
#define ROWS (B_SZ * S_LEN)       /* 8192 */
#define NTOT 128                  /* 64+32+32 */
#define INNER (D_MODEL * RANK)    /* 131072 */

// ---------------- scratch (device globals; no runtime allocation) ----------------
__device__ float g_wcat[NTOT * D_MODEL];
__device__ float g_logits[ROWS * NTOT];
__device__ float g_partial[256 * NTOT];
__device__ float g_accum[B_SZ * NTOT];
__device__ int   g_cidx[B_SZ * TOPK_C];
__device__ float g_cval[B_SZ * TOPK_C];
__device__ int   g_qidx[B_SZ * TOPK_QK];
__device__ float g_qval[B_SZ * TOPK_QK];
__device__ int   g_vidx[B_SZ * TOPK_V];
__device__ float g_vval[B_SZ * TOPK_V];
__device__ float g_SC[B_SZ * INNER];
__device__ float g_eQK[B_SZ * INNER];
__device__ float g_eV[B_SZ * INNER];
__device__ float g_h[B_SZ * S_LEN * RANK];
__device__ float g_Q[B_SZ * S_LEN * D_MODEL];
__device__ float g_V[B_SZ * S_LEN * D_MODEL];
__device__ float g_attn[B_SZ * S_LEN * D_MODEL];

// ---------------- concat router weights into one [128,1024] matrix ----------------
__global__ void concat_w_kernel(const float* __restrict__ Wc,
                                const float* __restrict__ Wq,
                                const float* __restrict__ Wv) {
    int i = blockIdx.x * blockDim.x + threadIdx.x;
    if (i >= NTOT * D_MODEL) return;
    int n = i >> 10, k = i & 1023;
    float v;
    if (n < 64)       v = Wc[n * D_MODEL + k];
    else if (n < 96)  v = Wq[(n - 64) * D_MODEL + k];
    else              v = Wv[(n - 96) * D_MODEL + k];
    g_wcat[i] = v;
}

// ---------------- generic 128x128x8 SGEMM, 8x8 microtile, optional B-transpose ----
// C[M,N] = A[M,K] * B  (B is [K,N] row-major if !BT, [N,K] row-major if BT)
template <bool BT>
__global__ __launch_bounds__(256) void sgemm_kernel(
    const float* __restrict__ A, const float* __restrict__ B, float* __restrict__ C,
    int M, int N, int K, long long sA, long long sB, long long sC) {
    A += (long long)blockIdx.z * sA;
    B += (long long)blockIdx.z * sB;
    C += (long long)blockIdx.z * sC;
    const int bm = blockIdx.y * 128, bn = blockIdx.x * 128;
    __shared__ float As[8][132];
    __shared__ float Bs[8][132];
    const int tid  = threadIdx.x;
    const int arow = tid >> 1, acol = (tid & 1) << 2;
    const int brow = tid >> 5, bcol = (tid & 31) << 2;
    const int ty = tid >> 4, tx = tid & 15;

    float acc[8][8];
#pragma unroll
    for (int i = 0; i < 8; i++)
#pragma unroll
        for (int j = 0; j < 8; j++) acc[i][j] = 0.f;

    for (int k0 = 0; k0 < K; k0 += 8) {
        float4 av = *(const float4*)(A + (long long)(bm + arow) * K + k0 + acol);
        As[acol + 0][arow] = av.x; As[acol + 1][arow] = av.y;
        As[acol + 2][arow] = av.z; As[acol + 3][arow] = av.w;
        if (BT) {
            float4 bv = *(const float4*)(B + (long long)(bn + arow) * K + k0 + acol);
            Bs[acol + 0][arow] = bv.x; Bs[acol + 1][arow] = bv.y;
            Bs[acol + 2][arow] = bv.z; Bs[acol + 3][arow] = bv.w;
        } else {
            float4 bv = *(const float4*)(B + (long long)(k0 + brow) * N + bn + bcol);
            *(float4*)&Bs[brow][bcol] = bv;
        }
        __syncthreads();
#pragma unroll
        for (int kk = 0; kk < 8; kk++) {
            float4 a0 = *(const float4*)&As[kk][ty * 4];
            float4 a1 = *(const float4*)&As[kk][64 + ty * 4];
            float4 b0 = *(const float4*)&Bs[kk][tx * 4];
            float4 b1 = *(const float4*)&Bs[kk][64 + tx * 4];
            float ra[8] = {a0.x, a0.y, a0.z, a0.w, a1.x, a1.y, a1.z, a1.w};
            float rb[8] = {b0.x, b0.y, b0.z, b0.w, b1.x, b1.y, b1.z, b1.w};
#pragma unroll
            for (int i = 0; i < 8; i++)
#pragma unroll
                for (int j = 0; j < 8; j++) acc[i][j] += ra[i] * rb[j];
        }
        __syncthreads();
    }
#pragma unroll
    for (int i = 0; i < 8; i++) {
        int m = bm + ((i < 4) ? ty * 4 + i : 64 + ty * 4 + (i - 4));
#pragma unroll
        for (int j = 0; j < 8; j++) {
            int n = bn + ((j < 4) ? tx * 4 + j : 64 + tx * 4 + (j - 4));
            C[(long long)m * N + n] = acc[i][j];
        }
    }
}

// ---------------- per-row group softmax * importance -> per-block partial sums ----
// 128 threads = one column n each; block handles 32 consecutive (b,s) rows.
__global__ __launch_bounds__(128) void softmax_accum_kernel(const float* __restrict__ importance) {
    const int n = threadIdx.x;
    const int warp = n >> 5, lane = n & 31;
    const int row0 = blockIdx.x * 32;
    __shared__ float red[8];
    float tot = 0.f;
    for (int r = 0; r < 32; r++) {
        const int gr = row0 + r;
        float lg = g_logits[gr * NTOT + n];
        float mx = lg;
#pragma unroll
        for (int off = 16; off; off >>= 1)
            mx = fmaxf(mx, __shfl_xor_sync(0xffffffffu, mx, off));
        if (lane == 0) red[warp] = mx;
        __syncthreads();
        float gmx = (n < 64) ? fmaxf(red[0], red[1]) : red[warp];
        float e = __expf(lg - gmx);
        float sm = e;
#pragma unroll
        for (int off = 16; off; off >>= 1)
            sm += __shfl_xor_sync(0xffffffffu, sm, off);
        if (lane == 0) red[4 + warp] = sm;
        __syncthreads();
        float gs = (n < 64) ? (red[4] + red[5]) : red[4 + warp];
        tot += importance[gr] * (e / gs);
        __syncthreads();
    }
    g_partial[blockIdx.x * NTOT + n] = tot;  // deterministic: no atomics
}

// ---------------- deterministic reduction of partials -> accum[b,n] --------------
__global__ void reduce_accum_kernel() {
    int i = threadIdx.x;  // 0..1023
    int b = i >> 7, n = i & 127;
    float s = 0.f;
#pragma unroll
    for (int c = 0; c < 32; c++) s += g_partial[(b * 32 + c) * NTOT + n];
    g_accum[i] = s;
}

// ---------------- top-k sparsify + renormalize (tiny) ----------------------------
__device__ void topk_group(const float* a, int n, int k, int* oidx, float* oval) {
    float v[64];
    for (int i = 0; i < n; i++) v[i] = a[i];
    float ssum = 0.f;
    for (int i = 0; i < k; i++) {
        int bj = 0; float bv = v[0];
        for (int j = 1; j < n; j++)
            if (v[j] > bv) { bv = v[j]; bj = j; }
        oidx[i] = bj; oval[i] = bv; v[bj] = -1e30f; ssum += bv;
    }
    float inv = 1.f / (ssum + 1e-8f);
    for (int i = 0; i < k; i++) oval[i] *= inv;
}

__global__ void topk_kernel() {
    int b = blockIdx.x, t = threadIdx.x;
    if (t == 0)      topk_group(&g_accum[b * NTOT],      64, TOPK_C,  &g_cidx[b * TOPK_C],  &g_cval[b * TOPK_C]);
    else if (t == 1) topk_group(&g_accum[b * NTOT + 64], 32, TOPK_QK, &g_qidx[b * TOPK_QK], &g_qval[b * TOPK_QK]);
    else if (t == 2) topk_group(&g_accum[b * NTOT + 96], 32, TOPK_V,  &g_vidx[b * TOPK_V],  &g_vval[b * TOPK_V]);
}

// ---------------- sparse weighted combine: out[b] = sum_t val[t] * src[idx[t]] ---
__global__ __launch_bounds__(256) void combine_kernel(const float* __restrict__ src,
                                                      float* __restrict__ out, int mode) {
    const int b = blockIdx.y;
    __shared__ int   si[8];
    __shared__ float sv[8];
    __shared__ int   skk;
    if (threadIdx.x == 0) {
        int k; const int* ip; const float* vp;
        if (mode == 0)      { k = TOPK_C;  ip = &g_cidx[b * TOPK_C];  vp = &g_cval[b * TOPK_C];  }
        else if (mode == 1) { k = TOPK_QK; ip = &g_qidx[b * TOPK_QK]; vp = &g_qval[b * TOPK_QK]; }
        else                { k = TOPK_V;  ip = &g_vidx[b * TOPK_V];  vp = &g_vval[b * TOPK_V];  }
        skk = k;
        for (int t = 0; t < k; t++) { si[t] = ip[t]; sv[t] = vp[t]; }
    }
    __syncthreads();
    const int k = skk;
    for (int i = blockIdx.x * 256 + threadIdx.x; i < INNER; i += gridDim.x * 256) {
        float s = 0.f;
        for (int t = 0; t < k; t++) s += sv[t] * src[(long long)si[t] * INNER + i];
        out[(long long)b * INNER + i] = s;
    }
}

// ---------------- causal flash attention, K == Q, dh = 64 ------------------------
// grid (16 qtiles, 16 heads, 8 batches), 256 threads (16x16).
// Each thread: 4 q-rows (4*ty..), 2 score cols (2*tx..), 4 out cols (4*tx..).
__global__ __launch_bounds__(256) void flash_kernel(const float* __restrict__ Qg,
                                                    const float* __restrict__ Vg,
                                                    float* __restrict__ Og) {
    const int b = blockIdx.z, h = blockIdx.y, qlo = blockIdx.x << 6;
    const float* Qb = Qg + ((long long)b << 20) + h * 64;
    const float* Vb = Vg + ((long long)b << 20) + h * 64;
    float* Ob = Og + ((long long)b << 20) + h * 64;
    __shared__ float Qs[64][68];  // [d][r]
    __shared__ float Ks[64][36];  // [d][j]
    __shared__ float Vs[32][68];  // [j][d]
    __shared__ float Ps[32][68];  // [j][r]
    const int tid = threadIdx.x, ty = tid >> 4, tx = tid & 15;

    for (int idx = tid; idx < 64 * 64; idx += 256) {
        int r = idx >> 6, d = idx & 63;
        Qs[d][r] = Qb[(long long)(qlo + r) * D_MODEL + d];
    }
    float m0[4], l0[4], oa[4][4];
#pragma unroll
    for (int i = 0; i < 4; i++) {
        m0[i] = -INFINITY; l0[i] = 0.f;
#pragma unroll
        for (int j = 0; j < 4; j++) oa[i][j] = 0.f;
    }
    __syncthreads();

    const int nkt = (qlo >> 5) + 2;  // k-tiles of 32 with klo <= qlo+63
    for (int kt = 0; kt < nkt; kt++) {
        const int klo = kt << 5;
        for (int idx = tid; idx < 32 * 64; idx += 256) {
            int j = idx >> 6, d = idx & 63;
            Ks[d][j] = Qb[(long long)(klo + j) * D_MODEL + d];  // K = Q
            Vs[j][d] = Vb[(long long)(klo + j) * D_MODEL + d];
        }
        __syncthreads();

        float s00 = 0, s01 = 0, s10 = 0, s11 = 0, s20 = 0, s21 = 0, s30 = 0, s31 = 0;
#pragma unroll 16
        for (int d = 0; d < 64; d++) {
            float4 q = *(const float4*)&Qs[d][ty << 2];
            float ka = Ks[d][tx << 1], kb = Ks[d][(tx << 1) + 1];
            s00 += q.x * ka; s01 += q.x * kb;
            s10 += q.y * ka; s11 += q.y * kb;
            s20 += q.z * ka; s21 += q.z * kb;
            s30 += q.w * ka; s31 += q.w * kb;
        }
        float svv[4][2] = {{s00, s01}, {s10, s11}, {s20, s21}, {s30, s31}};
#pragma unroll
        for (int i = 0; i < 4; i++) {
            const int qr = qlo + (ty << 2) + i;
            const int c0 = klo + (tx << 1);
            float a0 = (c0     <= qr) ? svv[i][0] * 0.125f : -INFINITY;
            float a1 = (c0 + 1 <= qr) ? svv[i][1] * 0.125f : -INFINITY;
            float rmax = fmaxf(a0, a1);
#pragma unroll
            for (int off = 8; off; off >>= 1)
                rmax = fmaxf(rmax, __shfl_xor_sync(0xffffffffu, rmax, off, 16));
            float mn = fmaxf(m0[i], rmax);
            float p0 = __expf(a0 - mn), p1 = __expf(a1 - mn);
            float rs = p0 + p1;
#pragma unroll
            for (int off = 8; off; off >>= 1)
                rs += __shfl_xor_sync(0xffffffffu, rs, off, 16);
            float alpha = __expf(m0[i] - mn);
            m0[i] = mn;
            l0[i] = l0[i] * alpha + rs;
#pragma unroll
            for (int j = 0; j < 4; j++) oa[i][j] *= alpha;
            Ps[(tx << 1)][(ty << 2) + i]     = p0;
            Ps[(tx << 1) + 1][(ty << 2) + i] = p1;
        }
        __syncthreads();

#pragma unroll 8
        for (int j = 0; j < 32; j++) {
            float4 p = *(const float4*)&Ps[j][ty << 2];
            float4 v = *(const float4*)&Vs[j][tx << 2];
            oa[0][0] += p.x * v.x; oa[0][1] += p.x * v.y; oa[0][2] += p.x * v.z; oa[0][3] += p.x * v.w;
            oa[1][0] += p.y * v.x; oa[1][1] += p.y * v.y; oa[1][2] += p.y * v.z; oa[1][3] += p.y * v.w;
            oa[2][0] += p.z * v.x; oa[2][1] += p.z * v.y; oa[2][2] += p.z * v.z; oa[2][3] += p.z * v.w;
            oa[3][0] += p.w * v.x; oa[3][1] += p.w * v.y; oa[3][2] += p.w * v.z; oa[3][3] += p.w * v.w;
        }
        __syncthreads();
    }
#pragma unroll
    for (int i = 0; i < 4; i++) {
        float inv = 1.f / l0[i];
        long long rowo = (long long)(qlo + (ty << 2) + i) * D_MODEL;
#pragma unroll
        for (int j = 0; j < 4; j++)
            Ob[rowo + (tx << 2) + j] = oa[i][j] * inv;
    }
}

// ---------------- launcher -------------------------------------------------------
extern "C" void kernel_launch(void* const* d_in, const int* in_sizes, int n_in,
                              void* d_out, int out_size) {
    (void)in_sizes; (void)n_in; (void)out_size;
    const float* x   = (const float*)d_in[0];
    const float* imp = (const float*)d_in[1];
    const float* Wc  = (const float*)d_in[2];
    const float* Wq  = (const float*)d_in[3];
    const float* Wv  = (const float*)d_in[4];
    const float* CN  = (const float*)d_in[5];
    const float* eQK = (const float*)d_in[6];
    const float* eV  = (const float*)d_in[7];
    const float* Wo  = (const float*)d_in[8];
    float* out = (float*)d_out;

    float *p_wcat, *p_logits, *p_SC, *p_eQK, *p_eV, *p_h, *p_Q, *p_V, *p_attn;
    cudaGetSymbolAddress((void**)&p_wcat,   g_wcat);
    cudaGetSymbolAddress((void**)&p_logits, g_logits);
    cudaGetSymbolAddress((void**)&p_SC,     g_SC);
    cudaGetSymbolAddress((void**)&p_eQK,    g_eQK);
    cudaGetSymbolAddress((void**)&p_eV,     g_eV);
    cudaGetSymbolAddress((void**)&p_h,      g_h);
    cudaGetSymbolAddress((void**)&p_Q,      g_Q);
    cudaGetSymbolAddress((void**)&p_V,      g_V);
    cudaGetSymbolAddress((void**)&p_attn,   g_attn);

    // 1. concat router weights
    concat_w_kernel<<<(NTOT * D_MODEL + 255) / 256, 256>>>(Wc, Wq, Wv);
    // 2. logits = x @ Wcat^T   [8192,128]
    sgemm_kernel<true><<<dim3(1, 64, 1), 256>>>(x, p_wcat, p_logits,
                                                ROWS, NTOT, D_MODEL, 0, 0, 0);
    // 3. grouped softmax * importance -> partials
    softmax_accum_kernel<<<256, 128>>>(imp);
    // 4. deterministic reduce
    reduce_accum_kernel<<<1, 1024>>>();
    // 5. top-k sparsify
    topk_kernel<<<B_SZ, 3>>>();
    // 6. sparse combines
    combine_kernel<<<dim3(128, B_SZ), 256>>>(CN,  p_SC,  0);
    combine_kernel<<<dim3(128, B_SZ), 256>>>(eQK, p_eQK, 1);
    combine_kernel<<<dim3(128, B_SZ), 256>>>(eV,  p_eV,  2);
    // 7. h = x @ SC   (batched over b)
    sgemm_kernel<false><<<dim3(1, 8, B_SZ), 256>>>(x, p_SC, p_h,
                                                   S_LEN, RANK, D_MODEL,
                                                   (long long)S_LEN * D_MODEL, INNER,
                                                   (long long)S_LEN * RANK);
    // 8. Q = h @ eQK, V = h @ eV   (batched)
    sgemm_kernel<false><<<dim3(8, 8, B_SZ), 256>>>(p_h, p_eQK, p_Q,
                                                   S_LEN, D_MODEL, RANK,
                                                   (long long)S_LEN * RANK, INNER,
                                                   (long long)S_LEN * D_MODEL);
    sgemm_kernel<false><<<dim3(8, 8, B_SZ), 256>>>(p_h, p_eV, p_V,
                                                   S_LEN, D_MODEL, RANK,
                                                   (long long)S_LEN * RANK, INNER,
                                                   (long long)S_LEN * D_MODEL);
    // 9. causal attention (K = Q)
    flash_kernel<<<dim3(16, N_HEADS, B_SZ), 256>>>(p_Q, p_V, p_attn);
    // 10. out = attn @ Wo^T
    sgemm_kernel<true><<<dim3(8, 64, 1), 256>>>(p_attn, Wo, out,
                                                ROWS, D_MODEL, D_MODEL, 0, 0, 0);
}

// round 2
// speedup vs baseline: 1.3694x; 1.3694x over previous
#include <cuda_runtime.h>
#include <math.h>
#include <stdint.h>

#define D_MODEL 1024
#define B_SZ 8
#define S_LEN 1024
#define N_HEADS 16
#define D_HEAD 64
#define RANK 128
#define N_COMPRESS 64
#define N_QK 32
#define N_V 32
#define TOPK_C 8
#define TOPK_QK 4
#define TOPK_V 6
#define ROWS (B_SZ * S_LEN)       /* 8192 */
#define NTOT 128                  /* 64+32+32 */
#define INNER (D_MODEL * RANK)    /* 131072 */

// ---------------- scratch (device globals; no runtime allocation) ----------------
__device__ float g_wcat[NTOT * D_MODEL];
__device__ float g_logits[ROWS * NTOT];
__device__ float g_partial[256 * NTOT];
__device__ float g_accum[B_SZ * NTOT];
__device__ int   g_cidx[B_SZ * TOPK_C];
__device__ float g_cval[B_SZ * TOPK_C];
__device__ int   g_qidx[B_SZ * TOPK_QK];
__device__ float g_qval[B_SZ * TOPK_QK];
__device__ int   g_vidx[B_SZ * TOPK_V];
__device__ float g_vval[B_SZ * TOPK_V];
__device__ float g_SC[B_SZ * INNER];
__device__ float g_eQK[B_SZ * INNER];
__device__ float g_eV[B_SZ * INNER];
__device__ float g_h[B_SZ * S_LEN * RANK];
__device__ float g_Q[B_SZ * S_LEN * D_MODEL];
__device__ float g_V[B_SZ * S_LEN * D_MODEL];
__device__ float g_attn[B_SZ * S_LEN * D_MODEL];

// ---------------- helpers --------------------------------------------------------
__device__ __forceinline__ float f2tf(float f) {
    uint32_t r;
    asm("cvt.rna.tf32.f32 %0, %1;" : "=r"(r) : "f"(f));
    return __uint_as_float(r);
}
__device__ __forceinline__ void mma_tf32(float c[4], uint32_t a0, uint32_t a1,
                                         uint32_t a2, uint32_t a3,
                                         uint32_t b0, uint32_t b1) {
    asm volatile(
        "mma.sync.aligned.m16n8k8.row.col.f32.tf32.tf32.f32 "
        "{%0,%1,%2,%3}, {%4,%5,%6,%7}, {%8,%9}, {%0,%1,%2,%3};\n"
        : "+f"(c[0]), "+f"(c[1]), "+f"(c[2]), "+f"(c[3])
        : "r"(a0), "r"(a1), "r"(a2), "r"(a3), "r"(b0), "r"(b1));
}

// ---------------- concat router weights into one [128,1024] matrix ----------------
__global__ void concat_w_kernel(const float* __restrict__ Wc,
                                const float* __restrict__ Wq,
                                const float* __restrict__ Wv) {
    int i = blockIdx.x * blockDim.x + threadIdx.x;
    if (i >= NTOT * D_MODEL) return;
    int n = i >> 10, k = i & 1023;
    float v;
    if (n < 64)       v = Wc[n * D_MODEL + k];
    else if (n < 96)  v = Wq[(n - 64) * D_MODEL + k];
    else              v = Wv[(n - 96) * D_MODEL + k];
    g_wcat[i] = v;
}

// ---------------- fp32 SGEMM (router logits only; determinism-critical) -----------
template <bool BT>
__global__ __launch_bounds__(256) void sgemm_kernel(
    const float* __restrict__ A, const float* __restrict__ B, float* __restrict__ C,
    int M, int N, int K, long long sA, long long sB, long long sC) {
    A += (long long)blockIdx.z * sA;
    B += (long long)blockIdx.z * sB;
    C += (long long)blockIdx.z * sC;
    const int bm = blockIdx.y * 128, bn = blockIdx.x * 128;
    __shared__ float As[8][132];
    __shared__ float Bs[8][132];
    const int tid  = threadIdx.x;
    const int arow = tid >> 1, acol = (tid & 1) << 2;
    const int brow = tid >> 5, bcol = (tid & 31) << 2;
    const int ty = tid >> 4, tx = tid & 15;

    float acc[8][8];
#pragma unroll
    for (int i = 0; i < 8; i++)
#pragma unroll
        for (int j = 0; j < 8; j++) acc[i][j] = 0.f;

    for (int k0 = 0; k0 < K; k0 += 8) {
        float4 av = *(const float4*)(A + (long long)(bm + arow) * K + k0 + acol);
        As[acol + 0][arow] = av.x; As[acol + 1][arow] = av.y;
        As[acol + 2][arow] = av.z; As[acol + 3][arow] = av.w;
        if (BT) {
            float4 bv = *(const float4*)(B + (long long)(bn + arow) * K + k0 + acol);
            Bs[acol + 0][arow] = bv.x; Bs[acol + 1][arow] = bv.y;
            Bs[acol + 2][arow] = bv.z; Bs[acol + 3][arow] = bv.w;
        } else {
            float4 bv = *(const float4*)(B + (long long)(k0 + brow) * N + bn + bcol);
            *(float4*)&Bs[brow][bcol] = bv;
        }
        __syncthreads();
#pragma unroll
        for (int kk = 0; kk < 8; kk++) {
            float4 a0 = *(const float4*)&As[kk][ty * 4];
            float4 a1 = *(const float4*)&As[kk][64 + ty * 4];
            float4 b0 = *(const float4*)&Bs[kk][tx * 4];
            float4 b1 = *(const float4*)&Bs[kk][64 + tx * 4];
            float ra[8] = {a0.x, a0.y, a0.z, a0.w, a1.x, a1.y, a1.z, a1.w};
            float rb[8] = {b0.x, b0.y, b0.z, b0.w, b1.x, b1.y, b1.z, b1.w};
#pragma unroll
            for (int i = 0; i < 8; i++)
#pragma unroll
                for (int j = 0; j < 8; j++) acc[i][j] += ra[i] * rb[j];
        }
        __syncthreads();
    }
#pragma unroll
    for (int i = 0; i < 8; i++) {
        int m = bm + ((i < 4) ? ty * 4 + i : 64 + ty * 4 + (i - 4));
#pragma unroll
        for (int j = 0; j < 8; j++) {
            int n = bn + ((j < 4) ? tx * 4 + j : 64 + tx * 4 + (j - 4));
            C[(long long)m * N + n] = acc[i][j];
        }
    }
}

// ---------------- TF32 tensor-core GEMM ------------------------------------------
// 128x128 block tile, 128 threads = 4 warps (2x2), 64x64 warp tile,
// mma.m16n8k8 tf32, inputs rounded to tf32 during gmem->smem copy.
// C[M,N] = A[M,K] * B  (B is [K,N] row-major if !BT, [N,K] row-major if BT)
template <bool BT>
__global__ __launch_bounds__(128) void tf32_gemm_kernel(
    const float* __restrict__ A, const float* __restrict__ B, float* __restrict__ C,
    int M, int N, int K, long long sA, long long sB, long long sC) {
    A += (long long)blockIdx.z * sA;
    B += (long long)blockIdx.z * sB;
    C += (long long)blockIdx.z * sC;
    const int bm = blockIdx.y * 128, bn = blockIdx.x * 128;
    __shared__ float As[128][20];   // [m][k], pad 4 -> conflict-free frag reads
    __shared__ float Bs[16][136];   // [k][n], pad 8 -> conflict-free frag reads
    const int tid = threadIdx.x;
    const int lane = tid & 31, wid = tid >> 5;
    const int wm = (wid >> 1) * 64;      // 0 / 64
    const int wn = (wid & 1) * 64;      // 0 / 64
    const int lr = lane >> 2, lc = lane & 3;

    float c[4][8][4];
#pragma unroll
    for (int t = 0; t < 4; t++)
#pragma unroll
        for (int u = 0; u < 8; u++)
#pragma unroll
            for (int r = 0; r < 4; r++) c[t][u][r] = 0.f;

    for (int k0 = 0; k0 < K; k0 += 16) {
        // load A chunk [128][16]
#pragma unroll
        for (int i = 0; i < 4; i++) {
            int idx = tid + i * 128;
            int row = idx >> 2, q = idx & 3;
            float4 v = *(const float4*)(A + (long long)(bm + row) * K + k0 + q * 4);
            float4 w = {f2tf(v.x), f2tf(v.y), f2tf(v.z), f2tf(v.w)};
            *(float4*)&As[row][q * 4] = w;
        }
        // load B chunk [16][128]
        if (!BT) {
#pragma unroll
            for (int i = 0; i < 4; i++) {
                int idx = tid + i * 128;
                int r = idx >> 5, cc = (idx & 31) * 4;
                float4 v = *(const float4*)(B + (long long)(k0 + r) * N + bn + cc);
                float4 w = {f2tf(v.x), f2tf(v.y), f2tf(v.z), f2tf(v.w)};
                *(float4*)&Bs[r][cc] = w;
            }
        } else {
#pragma unroll
            for (int i = 0; i < 4; i++) {
                int idx = tid + i * 128;
                int n = idx >> 2, q = idx & 3;
                float4 v = *(const float4*)(B + (long long)(bn + n) * K + k0 + q * 4);
                Bs[q * 4 + 0][n] = f2tf(v.x);
                Bs[q * 4 + 1][n] = f2tf(v.y);
                Bs[q * 4 + 2][n] = f2tf(v.z);
                Bs[q * 4 + 3][n] = f2tf(v.w);
            }
        }
        __syncthreads();
#pragma unroll
        for (int kk = 0; kk < 16; kk += 8) {
            uint32_t af[4][4];
#pragma unroll
            for (int t = 0; t < 4; t++) {
                int rb = wm + t * 16 + lr;
                int kc = kk + lc;
                af[t][0] = __float_as_uint(As[rb][kc]);
                af[t][1] = __float_as_uint(As[rb + 8][kc]);
                af[t][2] = __float_as_uint(As[rb][kc + 4]);
                af[t][3] = __float_as_uint(As[rb + 8][kc + 4]);
            }
            uint32_t bf[8][2];
#pragma unroll
            for (int u = 0; u < 8; u++) {
                int col = wn + u * 8 + lr;
                bf[u][0] = __float_as_uint(Bs[kk + lc][col]);
                bf[u][1] = __float_as_uint(Bs[kk + 4 + lc][col]);
            }
#pragma unroll
            for (int t = 0; t < 4; t++)
#pragma unroll
                for (int u = 0; u < 8; u++)
                    mma_tf32(c[t][u], af[t][0], af[t][1], af[t][2], af[t][3],
                             bf[u][0], bf[u][1]);
        }
        __syncthreads();
    }
    // epilogue
#pragma unroll
    for (int t = 0; t < 4; t++) {
        int row = bm + wm + t * 16 + lr;
#pragma unroll
        for (int u = 0; u < 8; u++) {
            int col = bn + wn + u * 8 + lc * 2;
            float2 v0 = {c[t][u][0], c[t][u][1]};
            float2 v1 = {c[t][u][2], c[t][u][3]};
            *(float2*)(C + (long long)row * N + col) = v0;
            *(float2*)(C + (long long)(row + 8) * N + col) = v1;
        }
    }
}

// ---------------- per-row group softmax * importance -> per-block partial sums ----
__global__ __launch_bounds__(128) void softmax_accum_kernel(const float* __restrict__ importance) {
    const int n = threadIdx.x;
    const int warp = n >> 5, lane = n & 31;
    const int row0 = blockIdx.x * 32;
    __shared__ float red[8];
    float tot = 0.f;
    for (int r = 0; r < 32; r++) {
        const int gr = row0 + r;
        float lg = g_logits[gr * NTOT + n];
        float mx = lg;
#pragma unroll
        for (int off = 16; off; off >>= 1)
            mx = fmaxf(mx, __shfl_xor_sync(0xffffffffu, mx, off));
        if (lane == 0) red[warp] = mx;
        __syncthreads();
        float gmx = (n < 64) ? fmaxf(red[0], red[1]) : red[warp];
        float e = __expf(lg - gmx);
        float sm = e;
#pragma unroll
        for (int off = 16; off; off >>= 1)
            sm += __shfl_xor_sync(0xffffffffu, sm, off);
        if (lane == 0) red[4 + warp] = sm;
        __syncthreads();
        float gs = (n < 64) ? (red[4] + red[5]) : red[4 + warp];
        tot += importance[gr] * (e / gs);
        __syncthreads();
    }
    g_partial[blockIdx.x * NTOT + n] = tot;  // deterministic: no atomics
}

// ---------------- deterministic reduction of partials -> accum[b,n] --------------
__global__ void reduce_accum_kernel() {
    int i = threadIdx.x;  // 0..1023
    int b = i >> 7, n = i & 127;
    float s = 0.f;
#pragma unroll
    for (int c = 0; c < 32; c++) s += g_partial[(b * 32 + c) * NTOT + n];
    g_accum[i] = s;
}

// ---------------- top-k sparsify + renormalize (tiny) ----------------------------
__device__ void topk_group(const float* a, int n, int k, int* oidx, float* oval) {
    float v[64];
    for (int i = 0; i < n; i++) v[i] = a[i];
    float ssum = 0.f;
    for (int i = 0; i < k; i++) {
        int bj = 0; float bv = v[0];
        for (int j = 1; j < n; j++)
            if (v[j] > bv) { bv = v[j]; bj = j; }
        oidx[i] = bj; oval[i] = bv; v[bj] = -1e30f; ssum += bv;
    }
    float inv = 1.f / (ssum + 1e-8f);
    for (int i = 0; i < k; i++) oval[i] *= inv;
}

__global__ void topk_kernel() {
    int b = blockIdx.x, t = threadIdx.x;
    if (t == 0)      topk_group(&g_accum[b * NTOT],      64, TOPK_C,  &g_cidx[b * TOPK_C],  &g_cval[b * TOPK_C]);
    else if (t == 1) topk_group(&g_accum[b * NTOT + 64], 32, TOPK_QK, &g_qidx[b * TOPK_QK], &g_qval[b * TOPK_QK]);
    else if (t == 2) topk_group(&g_accum[b * NTOT + 96], 32, TOPK_V,  &g_vidx[b * TOPK_V],  &g_vval[b * TOPK_V]);
}

// ---------------- sparse weighted combine: out[b] = sum_t val[t] * src[idx[t]] ---
__global__ __launch_bounds__(256) void combine_kernel(const float* __restrict__ src,
                                                      float* __restrict__ out, int mode) {
    const int b = blockIdx.y;
    __shared__ int   si[8];
    __shared__ float sv[8];
    __shared__ int   skk;
    if (threadIdx.x == 0) {
        int k; const int* ip; const float* vp;
        if (mode == 0)      { k = TOPK_C;  ip = &g_cidx[b * TOPK_C];  vp = &g_cval[b * TOPK_C];  }
        else if (mode == 1) { k = TOPK_QK; ip = &g_qidx[b * TOPK_QK]; vp = &g_qval[b * TOPK_QK]; }
        else                { k = TOPK_V;  ip = &g_vidx[b * TOPK_V];  vp = &g_vval[b * TOPK_V];  }
        skk = k;
        for (int t = 0; t < k; t++) { si[t] = ip[t]; sv[t] = vp[t]; }
    }
    __syncthreads();
    const int k = skk;
    for (int i = blockIdx.x * 256 + threadIdx.x; i < INNER; i += gridDim.x * 256) {
        float s = 0.f;
        for (int t = 0; t < k; t++) s += sv[t] * src[(long long)si[t] * INNER + i];
        out[(long long)b * INNER + i] = s;
    }
}

// ---------------- causal flash attention, K == Q, dh = 64 ------------------------
__global__ __launch_bounds__(256) void flash_kernel(const float* __restrict__ Qg,
                                                    const float* __restrict__ Vg,
                                                    float* __restrict__ Og) {
    const int b = blockIdx.z, h = blockIdx.y, qlo = blockIdx.x << 6;
    const float* Qb = Qg + ((long long)b << 20) + h * 64;
    const float* Vb = Vg + ((long long)b << 20) + h * 64;
    float* Ob = Og + ((long long)b << 20) + h * 64;
    __shared__ float Qs[64][68];  // [d][r]
    __shared__ float Ks[64][36];  // [d][j]
    __shared__ float Vs[32][68];  // [j][d]
    __shared__ float Ps[32][68];  // [j][r]
    const int tid = threadIdx.x, ty = tid >> 4, tx = tid & 15;

    for (int idx = tid; idx < 64 * 64; idx += 256) {
        int r = idx >> 6, d = idx & 63;
        Qs[d][r] = Qb[(long long)(qlo + r) * D_MODEL + d];
    }
    float m0[4], l0[4], oa[4][4];
#pragma unroll
    for (int i = 0; i < 4; i++) {
        m0[i] = -INFINITY; l0[i] = 0.f;
#pragma unroll
        for (int j = 0; j < 4; j++) oa[i][j] = 0.f;
    }
    __syncthreads();

    const int nkt = (qlo >> 5) + 2;  // k-tiles of 32 with klo <= qlo+63
    for (int kt = 0; kt < nkt; kt++) {
        const int klo = kt << 5;
        for (int idx = tid; idx < 32 * 64; idx += 256) {
            int j = idx >> 6, d = idx & 63;
            Ks[d][j] = Qb[(long long)(klo + j) * D_MODEL + d];  // K = Q
            Vs[j][d] = Vb[(long long)(klo + j) * D_MODEL + d];
        }
        __syncthreads();

        float s00 = 0, s01 = 0, s10 = 0, s11 = 0, s20 = 0, s21 = 0, s30 = 0, s31 = 0;
#pragma unroll 16
        for (int d = 0; d < 64; d++) {
            float4 q = *(const float4*)&Qs[d][ty << 2];
            float ka = Ks[d][tx << 1], kb = Ks[d][(tx << 1) + 1];
            s00 += q.x * ka; s01 += q.x * kb;
            s10 += q.y * ka; s11 += q.y * kb;
            s20 += q.z * ka; s21 += q.z * kb;
            s30 += q.w * ka; s31 += q.w * kb;
        }
        float svv[4][2] = {{s00, s01}, {s10, s11}, {s20, s21}, {s30, s31}};
#pragma unroll
        for (int i = 0; i < 4; i++) {
            const int qr = qlo + (ty << 2) + i;
            const int c0 = klo + (tx << 1);
            float a0 = (c0     <= qr) ? svv[i][0] * 0.125f : -INFINITY;
            float a1 = (c0 + 1 <= qr) ? svv[i][1] * 0.125f : -INFINITY;
            float rmax = fmaxf(a0, a1);
#pragma unroll
            for (int off = 8; off; off >>= 1)
                rmax = fmaxf(rmax, __shfl_xor_sync(0xffffffffu, rmax, off, 16));
            float mn = fmaxf(m0[i], rmax);
            float p0 = __expf(a0 - mn), p1 = __expf(a1 - mn);
            float rs = p0 + p1;
#pragma unroll
            for (int off = 8; off; off >>= 1)
                rs += __shfl_xor_sync(0xffffffffu, rs, off, 16);
            float alpha = __expf(m0[i] - mn);
            m0[i] = mn;
            l0[i] = l0[i] * alpha + rs;
#pragma unroll
            for (int j = 0; j < 4; j++) oa[i][j] *= alpha;
            Ps[(tx << 1)][(ty << 2) + i]     = p0;
            Ps[(tx << 1) + 1][(ty << 2) + i] = p1;
        }
        __syncthreads();

#pragma unroll 8
        for (int j = 0; j < 32; j++) {
            float4 p = *(const float4*)&Ps[j][ty << 2];
            float4 v = *(const float4*)&Vs[j][tx << 2];
            oa[0][0] += p.x * v.x; oa[0][1] += p.x * v.y; oa[0][2] += p.x * v.z; oa[0][3] += p.x * v.w;
            oa[1][0] += p.y * v.x; oa[1][1] += p.y * v.y; oa[1][2] += p.y * v.z; oa[1][3] += p.y * v.w;
            oa[2][0] += p.z * v.x; oa[2][1] += p.z * v.y; oa[2][2] += p.z * v.z; oa[2][3] += p.z * v.w;
            oa[3][0] += p.w * v.x; oa[3][1] += p.w * v.y; oa[3][2] += p.w * v.z; oa[3][3] += p.w * v.w;
        }
        __syncthreads();
    }
#pragma unroll
    for (int i = 0; i < 4; i++) {
        float inv = 1.f / l0[i];
        long long rowo = (long long)(qlo + (ty << 2) + i) * D_MODEL;
#pragma unroll
        for (int j = 0; j < 4; j++)
            Ob[rowo + (tx << 2) + j] = oa[i][j] * inv;
    }
}

// ---------------- launcher -------------------------------------------------------
extern "C" void kernel_launch(void* const* d_in, const int* in_sizes, int n_in,
                              void* d_out, int out_size) {
    (void)in_sizes; (void)n_in; (void)out_size;
    const float* x   = (const float*)d_in[0];
    const float* imp = (const float*)d_in[1];
    const float* Wc  = (const float*)d_in[2];
    const float* Wq  = (const float*)d_in[3];
    const float* Wv  = (const float*)d_in[4];
    const float* CN  = (const float*)d_in[5];
    const float* eQK = (const float*)d_in[6];
    const float* eV  = (const float*)d_in[7];
    const float* Wo  = (const float*)d_in[8];
    float* out = (float*)d_out;

    float *p_wcat, *p_logits, *p_SC, *p_eQK, *p_eV, *p_h, *p_Q, *p_V, *p_attn;
    cudaGetSymbolAddress((void**)&p_wcat,   g_wcat);
    cudaGetSymbolAddress((void**)&p_logits, g_logits);
    cudaGetSymbolAddress((void**)&p_SC,     g_SC);
    cudaGetSymbolAddress((void**)&p_eQK,    g_eQK);
    cudaGetSymbolAddress((void**)&p_eV,     g_eV);
    cudaGetSymbolAddress((void**)&p_h,      g_h);
    cudaGetSymbolAddress((void**)&p_Q,      g_Q);
    cudaGetSymbolAddress((void**)&p_V,      g_V);
    cudaGetSymbolAddress((void**)&p_attn,   g_attn);

    // 1. concat router weights
    concat_w_kernel<<<(NTOT * D_MODEL + 255) / 256, 256>>>(Wc, Wq, Wv);
    // 2. logits = x @ Wcat^T   [8192,128]  (fp32: top-k determinism)
    sgemm_kernel<true><<<dim3(1, 64, 1), 256>>>(x, p_wcat, p_logits,
                                                ROWS, NTOT, D_MODEL, 0, 0, 0);
    // 3. grouped softmax * importance -> partials
    softmax_accum_kernel<<<256, 128>>>(imp);
    // 4. deterministic reduce
    reduce_accum_kernel<<<1, 1024>>>();
    // 5. top-k sparsify
    topk_kernel<<<B_SZ, 3>>>();
    // 6. sparse combines
    combine_kernel<<<dim3(128, B_SZ), 256>>>(CN,  p_SC,  0);
    combine_kernel<<<dim3(128, B_SZ), 256>>>(eQK, p_eQK, 1);
    combine_kernel<<<dim3(128, B_SZ), 256>>>(eV,  p_eV,  2);
    // 7. h = x @ SC   (batched over b)  [tf32 tensor cores]
    tf32_gemm_kernel<false><<<dim3(1, 8, B_SZ), 128>>>(x, p_SC, p_h,
                                                       S_LEN, RANK, D_MODEL,
                                                       (long long)S_LEN * D_MODEL, INNER,
                                                       (long long)S_LEN * RANK);
    // 8. Q = h @ eQK, V = h @ eV   (batched)  [tf32]
    tf32_gemm_kernel<false><<<dim3(8, 8, B_SZ), 128>>>(p_h, p_eQK, p_Q,
                                                       S_LEN, D_MODEL, RANK,
                                                       (long long)S_LEN * RANK, INNER,
                                                       (long long)S_LEN * D_MODEL);
    tf32_gemm_kernel<false><<<dim3(8, 8, B_SZ), 128>>>(p_h, p_eV, p_V,
                                                       S_LEN, D_MODEL, RANK,
                                                       (long long)S_LEN * RANK, INNER,
                                                       (long long)S_LEN * D_MODEL);
    // 9. causal attention (K = Q)  (fp32 this round)
    flash_kernel<<<dim3(16, N_HEADS, B_SZ), 256>>>(p_Q, p_V, p_attn);
    // 10. out = attn @ Wo^T  [tf32]
    tf32_gemm_kernel<true><<<dim3(8, 64, 1), 128>>>(p_attn, Wo, out,
                                                    ROWS, D_MODEL, D_MODEL, 0, 0, 0);
}